// round 1
// baseline (speedup 1.0000x reference)
#include <cuda_runtime.h>
#include <cuda_bf16.h>
#include <math.h>

#define MAX_NODES 50000
#define D 64
#define B 64
#define HL 128

// ---------------- scratch (device globals; no allocation) ----------------
__device__ __align__(16) float4 g_agg4[MAX_NODES * 16];    // [N,64] f32 as float4
__device__ __align__(16) float4 g_h4[MAX_NODES * 16];      // [N,64] f32
__device__ __align__(16) float g_sums[B * D];              // pooled sums
__device__ float g_cnt[B];
__device__ __align__(16) float g_gates[B * 4 * HL];

// ---------------- zero kernels ----------------
__global__ void zero4_kernel(float4* p, int n4) {
    int i = blockIdx.x * blockDim.x + threadIdx.x;
    if (i < n4) p[i] = make_float4(0.f, 0.f, 0.f, 0.f);
}

__global__ void zero_pool_kernel(float* sums, float* cnt) {
    int i = blockIdx.x * blockDim.x + threadIdx.x;
    if (i < B * D) sums[i] = 0.f;
    if (i < B) cnt[i] = 0.f;
}

// ---------------- edge scatter: agg[dst] += feat[src] ----------------
// 8 threads per edge; each handles 8 consecutive floats (2 float4) -> fully
// coalesced 256B row reads; vectorized red.global.add.v4.f32 atomics.
__device__ __forceinline__ void red_add_v4(float* p, float4 v) {
    asm volatile("red.global.add.v4.f32 [%0], {%1,%2,%3,%4};"
                 :: "l"(p), "f"(v.x), "f"(v.y), "f"(v.z), "f"(v.w) : "memory");
}

__global__ void scatter_kernel(const float* __restrict__ feat,
                               const int* __restrict__ ei, int n_edges,
                               float* __restrict__ agg) {
    int tid = blockIdx.x * blockDim.x + threadIdx.x;
    int e = tid >> 3;
    int c = tid & 7;
    if (e >= n_edges) return;
    int s = __ldg(ei + e);
    int d = __ldg(ei + n_edges + e);
    const float4* sp = (const float4*)(feat + (size_t)s * 64 + c * 8);
    float4 v0 = __ldg(sp);
    float4 v1 = __ldg(sp + 1);
    float* dp = agg + (size_t)d * 64 + c * 8;
    red_add_v4(dp, v0);
    red_add_v4(dp + 4, v1);
}

// ---------------- fused GIN MLP: out = relu(relu((x+agg)@wA.T+bA)@wB.T+bB) ----
// warp processes 4 rows; lane computes cols (lane, lane+32); k rotated per lane
// so both weight and row smem reads are bank-conflict-free.
#define GIN_WARPS 8
__global__ void __launch_bounds__(256) gin_kernel(
        const float* __restrict__ xin, const float* __restrict__ agg,
        const float* __restrict__ wA, const float* __restrict__ bA,
        const float* __restrict__ wB, const float* __restrict__ bB,
        float* __restrict__ out, int n) {
    __shared__ float wAs[64 * 64];
    __shared__ float wBs[64 * 64];
    __shared__ float bAs[64], bBs[64];
    __shared__ float rows[GIN_WARPS][4][64];
    __shared__ float ts[GIN_WARPS][4][64];

    int tid = threadIdx.x;
    for (int i = tid; i < 4096; i += 256) { wAs[i] = wA[i]; wBs[i] = wB[i]; }
    if (tid < 64) { bAs[tid] = bA[tid]; bBs[tid] = bB[tid]; }
    __syncthreads();

    int warp = tid >> 5, lane = tid & 31;
    int j0 = lane, j1 = lane + 32;
    int ngroups = (n + 3) >> 2;
    int gw = blockIdx.x * GIN_WARPS + warp;
    int stride = gridDim.x * GIN_WARPS;

    for (int g = gw; g < ngroups; g += stride) {
        int r0 = g * 4;
        int nr = min(4, n - r0);
        for (int i = 0; i < nr; i++) {
            const float2* xr = (const float2*)(xin + (size_t)(r0 + i) * 64);
            const float2* ar = (const float2*)(agg + (size_t)(r0 + i) * 64);
            float2 xa = __ldg(xr + lane);
            float2 aa = ar[lane];
            rows[warp][i][lane * 2] = xa.x + aa.x;
            rows[warp][i][lane * 2 + 1] = xa.y + aa.y;
        }
        // ensure unused rows hold finite values (results discarded, avoid NaN traps)
        for (int i = nr; i < 4; i++) {
            rows[warp][i][lane * 2] = 0.f;
            rows[warp][i][lane * 2 + 1] = 0.f;
        }
        __syncwarp();

        float acc[4][2];
#pragma unroll
        for (int i = 0; i < 4; i++) { acc[i][0] = bAs[j0]; acc[i][1] = bAs[j1]; }
#pragma unroll 8
        for (int kk = 0; kk < 64; kk++) {
            int k = (kk + lane) & 63;
            float w0 = wAs[j0 * 64 + k];
            float w1 = wAs[j1 * 64 + k];
#pragma unroll
            for (int i = 0; i < 4; i++) {
                float h = rows[warp][i][k];
                acc[i][0] += h * w0;
                acc[i][1] += h * w1;
            }
        }
#pragma unroll
        for (int i = 0; i < 4; i++) {
            ts[warp][i][j0] = fmaxf(acc[i][0], 0.f);
            ts[warp][i][j1] = fmaxf(acc[i][1], 0.f);
        }
        __syncwarp();

#pragma unroll
        for (int i = 0; i < 4; i++) { acc[i][0] = bBs[j0]; acc[i][1] = bBs[j1]; }
#pragma unroll 8
        for (int kk = 0; kk < 64; kk++) {
            int k = (kk + lane) & 63;
            float w0 = wBs[j0 * 64 + k];
            float w1 = wBs[j1 * 64 + k];
#pragma unroll
            for (int i = 0; i < 4; i++) {
                float t = ts[warp][i][k];
                acc[i][0] += t * w0;
                acc[i][1] += t * w1;
            }
        }
        for (int i = 0; i < nr; i++) {
            out[(size_t)(r0 + i) * 64 + j0] = fmaxf(acc[i][0], 0.f);
            out[(size_t)(r0 + i) * 64 + j1] = fmaxf(acc[i][1], 0.f);
        }
        __syncwarp();
    }
}

// ---------------- mean-pool over sorted batch ----------------
#define POOL_CHUNK 512
__global__ void pool_kernel(const float* __restrict__ h,
                            const int* __restrict__ batch, int n,
                            float* __restrict__ sums, float* __restrict__ cnt) {
    int d = threadIdx.x;  // 64 threads
    int start = blockIdx.x * POOL_CHUNK;
    if (start >= n) return;
    int end = min(start + POOL_CHUNK, n);
    int cur = __ldg(batch + start);
    float acc = 0.f, c = 0.f;
    for (int r = start; r < end; r++) {
        int b = __ldg(batch + r);
        if (b != cur) {
            atomicAdd(&sums[cur * 64 + d], acc);
            if (d == 0) atomicAdd(&cnt[cur], c);
            acc = 0.f; c = 0.f; cur = b;
        }
        acc += h[(size_t)r * 64 + d];
        c += 1.f;
    }
    atomicAdd(&sums[cur * 64 + d], acc);
    if (d == 0) atomicAdd(&cnt[cur], c);
}

// ---------------- LSTM gate GEMM: gates[b][j] ----------------
__global__ void __launch_bounds__(512) gates_kernel(
        const float* __restrict__ sums, const float* __restrict__ cnt,
        const float* __restrict__ h0,
        const float* __restrict__ w_ih, const float* __restrict__ w_hh,
        const float* __restrict__ b_ih, const float* __restrict__ b_hh,
        float* __restrict__ gates) {
    int b = blockIdx.x;
    int j = threadIdx.x;  // 512
    __shared__ float ps[64];
    __shared__ float h0s[128];
    if (j < 64) ps[j] = sums[b * 64 + j] / fmaxf(cnt[b], 1.f);
    if (j >= 64 && j < 192) h0s[j - 64] = h0[b * 128 + (j - 64)];
    __syncthreads();

    float acc = b_ih[j] + b_hh[j];
    const float4* wi = (const float4*)(w_ih + (size_t)j * 64);
#pragma unroll
    for (int k4 = 0; k4 < 16; k4++) {
        float4 w = __ldg(wi + k4);
        acc += w.x * ps[k4 * 4] + w.y * ps[k4 * 4 + 1]
             + w.z * ps[k4 * 4 + 2] + w.w * ps[k4 * 4 + 3];
    }
    const float4* wh = (const float4*)(w_hh + (size_t)j * 128);
#pragma unroll
    for (int k4 = 0; k4 < 32; k4++) {
        float4 w = __ldg(wh + k4);
        acc += w.x * h0s[k4 * 4] + w.y * h0s[k4 * 4 + 1]
             + w.z * h0s[k4 * 4 + 2] + w.w * h0s[k4 * 4 + 3];
    }
    gates[b * 512 + j] = acc;
}

// ---------------- LSTM cell + FC + softmax; writes all outputs ----------------
__global__ void lstm_fc_kernel(const float* __restrict__ gates,
                               const float* __restrict__ c0,
                               const float* __restrict__ fc_w,
                               const float* __restrict__ fc_b,
                               float* __restrict__ out) {
    int b = blockIdx.x;
    int t = threadIdx.x;  // 128
    __shared__ float h1s[128];
    const float* gb = gates + b * 512;
    float gi = gb[t], gf = gb[128 + t], gg = gb[256 + t], go = gb[384 + t];
    float si = 1.f / (1.f + expf(-gi));
    float sf = 1.f / (1.f + expf(-gf));
    float so = 1.f / (1.f + expf(-go));
    float c1 = sf * c0[b * 128 + t] + si * tanhf(gg);
    float h1 = so * tanhf(c1);
    out[B * 32 + b * 128 + t] = h1;                 // h1 block
    out[B * 32 + B * 128 + b * 128 + t] = c1;       // c1 block
    h1s[t] = h1;
    __syncthreads();
    if (t < 32) {
        float acc = fc_b[t];
        const float4* fw = (const float4*)(fc_w + (size_t)t * 128);
#pragma unroll
        for (int k4 = 0; k4 < 32; k4++) {
            float4 w = __ldg(fw + k4);
            acc += w.x * h1s[k4 * 4] + w.y * h1s[k4 * 4 + 1]
                 + w.z * h1s[k4 * 4 + 2] + w.w * h1s[k4 * 4 + 3];
        }
        float m = acc;
        for (int off = 16; off; off >>= 1)
            m = fmaxf(m, __shfl_xor_sync(0xffffffffu, m, off));
        float e = expf(acc - m);
        float s = e;
        for (int off = 16; off; off >>= 1)
            s += __shfl_xor_sync(0xffffffffu, s, off);
        out[b * 32 + t] = e / s;
    }
}

// ---------------- launch ----------------
extern "C" void kernel_launch(void* const* d_in, const int* in_sizes, int n_in,
                              void* d_out, int out_size) {
    const float* x     = (const float*)d_in[0];
    const int*   ei    = (const int*)d_in[1];
    const int*   batch = (const int*)d_in[2];
    const float* w1    = (const float*)d_in[3];
    const float* b1    = (const float*)d_in[4];
    const float* w2    = (const float*)d_in[5];
    const float* b2    = (const float*)d_in[6];
    const float* w3    = (const float*)d_in[7];
    const float* b3    = (const float*)d_in[8];
    const float* w4    = (const float*)d_in[9];
    const float* b4    = (const float*)d_in[10];
    const float* w_ih  = (const float*)d_in[11];
    const float* w_hh  = (const float*)d_in[12];
    const float* b_ih  = (const float*)d_in[13];
    const float* b_hh  = (const float*)d_in[14];
    const float* fc_w  = (const float*)d_in[15];
    const float* fc_b  = (const float*)d_in[16];
    const float* h0    = (const float*)d_in[17];
    const float* c0    = (const float*)d_in[18];
    float* out = (float*)d_out;

    int n_nodes = in_sizes[0] / 64;
    int n_edges = in_sizes[1] / 2;

    float4* agg4; cudaGetSymbolAddress((void**)&agg4, g_agg4);
    float4* h4;   cudaGetSymbolAddress((void**)&h4, g_h4);
    float* sums;  cudaGetSymbolAddress((void**)&sums, g_sums);
    float* cnt;   cudaGetSymbolAddress((void**)&cnt, g_cnt);
    float* gates; cudaGetSymbolAddress((void**)&gates, g_gates);
    float* agg = (float*)agg4;
    float* hbuf = (float*)h4;

    int n4 = n_nodes * 16;
    int zb = (n4 + 255) / 256;
    int sb = (n_edges * 8 + 255) / 256;
    int gin_blocks = 592;  // 148 SMs * 4

    // ---- layer 1 ----
    zero4_kernel<<<zb, 256>>>(agg4, n4);
    scatter_kernel<<<sb, 256>>>(x, ei, n_edges, agg);
    gin_kernel<<<gin_blocks, 256>>>(x, agg, w1, b1, w2, b2, hbuf, n_nodes);

    // ---- layer 2 ----
    zero4_kernel<<<zb, 256>>>(agg4, n4);
    scatter_kernel<<<sb, 256>>>(hbuf, ei, n_edges, agg);
    gin_kernel<<<gin_blocks, 256>>>(hbuf, agg, w3, b3, w4, b4, hbuf, n_nodes);

    // ---- pooling ----
    zero_pool_kernel<<<17, 256>>>(sums, cnt);
    int pb = (n_nodes + POOL_CHUNK - 1) / POOL_CHUNK;
    pool_kernel<<<pb, 64>>>(hbuf, batch, n_nodes, sums, cnt);

    // ---- LSTM + FC + softmax ----
    gates_kernel<<<B, 512>>>(sums, cnt, h0, w_ih, w_hh, b_ih, b_hh, gates);
    lstm_fc_kernel<<<B, 128>>>(gates, c0, fc_w, fc_b, out);
}

// round 2
// speedup vs baseline: 1.0701x; 1.0701x over previous
#include <cuda_runtime.h>
#include <math.h>

#define MAX_NODES 50000
#define MAX_EDGES 800000
#define D 64
#define B 64
#define HL 128
#define NCH 512
#define POOL_CHUNK 1024

// ---------------- scratch (device globals; no allocation) ----------------
__device__ int g_counts[MAX_NODES];
__device__ int g_offs[MAX_NODES];
__device__ int g_cursor[MAX_NODES];
__device__ int g_chunkbase[NCH];
__device__ int g_elist[MAX_EDGES];
__device__ __align__(16) float g_hs[MAX_NODES * D];   // gather output (x + sum)
__device__ __align__(16) float g_h1[MAX_NODES * D];   // gin output
__device__ __align__(16) float g_sums[B * D];
__device__ float g_cnt[B];
__device__ __align__(16) float g_gates[B * 4 * HL];

// ---------------- zero counts + pool accumulators ----------------
__global__ void zero_all_kernel(int* counts, float* sums, float* cnt, int n_nodes) {
    int i = blockIdx.x * blockDim.x + threadIdx.x;
    if (i < n_nodes) counts[i] = 0;
    if (i < B * D) sums[i] = 0.f;
    if (i < B) cnt[i] = 0.f;
}

// ---------------- CSR build ----------------
__global__ void count_kernel(const int* __restrict__ ei, int n_edges,
                             int* __restrict__ counts) {
    int e = blockIdx.x * blockDim.x + threadIdx.x;
    if (e < n_edges) atomicAdd(&counts[__ldg(ei + n_edges + e)], 1);
}

__global__ void scan1_kernel(const int* __restrict__ counts, int n,
                             int* __restrict__ chunkbase) {
    __shared__ int sm[NCH];
    int t = threadIdx.x;
    int per = (n + NCH - 1) / NCH;
    int lo = t * per, hi = min(lo + per, n);
    int s = 0;
    for (int i = lo; i < hi; i++) s += counts[i];
    sm[t] = s;
    __syncthreads();
    for (int off = 1; off < NCH; off <<= 1) {
        int v = (t >= off) ? sm[t - off] : 0;
        __syncthreads();
        sm[t] += v;
        __syncthreads();
    }
    chunkbase[t] = sm[t] - s;  // exclusive
}

__global__ void scan2_kernel(const int* __restrict__ counts, int n,
                             const int* __restrict__ chunkbase,
                             int* __restrict__ offs, int* __restrict__ cursor) {
    int t = blockIdx.x * blockDim.x + threadIdx.x;
    if (t >= NCH) return;
    int per = (n + NCH - 1) / NCH;
    int lo = t * per, hi = min(lo + per, n);
    int base = chunkbase[t];
    for (int i = lo; i < hi; i++) {
        offs[i] = base;
        cursor[i] = base;
        base += counts[i];
    }
}

__global__ void fill_kernel(const int* __restrict__ ei, int n_edges,
                            int* __restrict__ cursor, int* __restrict__ elist) {
    int e = blockIdx.x * blockDim.x + threadIdx.x;
    if (e < n_edges) {
        int s = __ldg(ei + e);
        int d = __ldg(ei + n_edges + e);
        int p = atomicAdd(&cursor[d], 1);
        elist[p] = s;
    }
}

// ---------------- CSR gather: outh[i] = x[i] + sum_{j in N(i)} feat[j] ----
__global__ void __launch_bounds__(256) gather_kernel(
        const float* __restrict__ feat, const float* __restrict__ xin,
        const int* __restrict__ elist, const int* __restrict__ offs,
        const int* __restrict__ counts, float* __restrict__ outh, int n) {
    int w = (blockIdx.x * blockDim.x + threadIdx.x) >> 5;
    int lane = threadIdx.x & 31;
    if (w >= n) return;
    int start = __ldg(offs + w);
    int deg = __ldg(counts + w);
    float2 a0 = ((const float2*)(xin + (size_t)w * 64))[lane];
    float2 a1 = make_float2(0.f, 0.f);
    float2 a2 = make_float2(0.f, 0.f);
    float2 a3 = make_float2(0.f, 0.f);
    int e = 0;
    for (; e + 3 < deg; e += 4) {
        int s0 = __ldg(elist + start + e);
        int s1 = __ldg(elist + start + e + 1);
        int s2 = __ldg(elist + start + e + 2);
        int s3 = __ldg(elist + start + e + 3);
        float2 v0 = ((const float2*)(feat + (size_t)s0 * 64))[lane];
        float2 v1 = ((const float2*)(feat + (size_t)s1 * 64))[lane];
        float2 v2 = ((const float2*)(feat + (size_t)s2 * 64))[lane];
        float2 v3 = ((const float2*)(feat + (size_t)s3 * 64))[lane];
        a0.x += v0.x; a0.y += v0.y;
        a1.x += v1.x; a1.y += v1.y;
        a2.x += v2.x; a2.y += v2.y;
        a3.x += v3.x; a3.y += v3.y;
    }
    for (; e < deg; e++) {
        int s0 = __ldg(elist + start + e);
        float2 v0 = ((const float2*)(feat + (size_t)s0 * 64))[lane];
        a0.x += v0.x; a0.y += v0.y;
    }
    float2 r = make_float2(a0.x + a1.x + a2.x + a3.x,
                           a0.y + a1.y + a2.y + a3.y);
    ((float2*)(outh + (size_t)w * 64))[lane] = r;
}

// ---------------- fused GIN MLP via packed f32x2 FMA ----------------
// out = relu(relu(hs @ wA.T + bA) @ wB.T + bB); warp handles 8 rows.
// Row k-pairs: broadcast ld.shared.b64; weights: packed float4
// {w[j0][k], w[j0][k+1], w[j1][k], w[j1][k+1]} read as ld.shared.v2.u64.
#define GIN_SMEM_FLOATS 16512  // wA4 4096 + wB4 4096 + rows 4096 + ts 4096 + 128

__device__ __forceinline__ void ffma2(unsigned long long& acc,
                                      unsigned long long a, unsigned long long b) {
    asm("fma.rn.f32x2 %0, %1, %2, %3;" : "=l"(acc) : "l"(a), "l"(b), "l"(acc));
}
__device__ __forceinline__ float f32x2_sum(unsigned long long v) {
    float lo = __uint_as_float((unsigned)(v & 0xffffffffull));
    float hi = __uint_as_float((unsigned)(v >> 32));
    return lo + hi;
}

__global__ void __launch_bounds__(256) gin_kernel(
        const float* __restrict__ hs,
        const float* __restrict__ wA, const float* __restrict__ bA,
        const float* __restrict__ wB, const float* __restrict__ bB,
        float* __restrict__ out, int n) {
    extern __shared__ float smem[];
    float4* wA4 = (float4*)smem;                  // 1024 float4
    float4* wB4 = (float4*)(smem + 4096);         // 1024 float4
    float* rowsbuf = smem + 8192;                 // 8 warps * 512
    float* tsbuf = smem + 12288;                  // 8 warps * 512
    float* bAs = smem + 16384;
    float* bBs = smem + 16448;

    int tid = threadIdx.x, warp = tid >> 5, lane = tid & 31;
    for (int idx = tid; idx < 1024; idx += 256) {
        int j0 = idx & 31, k = (idx >> 5) * 2;
        wA4[idx] = make_float4(wA[j0 * 64 + k], wA[j0 * 64 + k + 1],
                               wA[(j0 + 32) * 64 + k], wA[(j0 + 32) * 64 + k + 1]);
        wB4[idx] = make_float4(wB[j0 * 64 + k], wB[j0 * 64 + k + 1],
                               wB[(j0 + 32) * 64 + k], wB[(j0 + 32) * 64 + k + 1]);
    }
    if (tid < 64) { bAs[tid] = bA[tid]; bBs[tid] = bB[tid]; }
    __syncthreads();

    float* rows = rowsbuf + warp * 512;
    float* ts = tsbuf + warp * 512;
    unsigned rows_a = (unsigned)__cvta_generic_to_shared(rows);
    unsigned ts_a = (unsigned)__cvta_generic_to_shared(ts);
    unsigned wA_a = (unsigned)__cvta_generic_to_shared(wA4);
    unsigned wB_a = (unsigned)__cvta_generic_to_shared(wB4);

    float bAj0 = bAs[lane], bAj1 = bAs[lane + 32];
    float bBj0 = bBs[lane], bBj1 = bBs[lane + 32];

    int ngroups = (n + 7) >> 3;
    for (int g = blockIdx.x * 8 + warp; g < ngroups; g += gridDim.x * 8) {
        int r0 = g * 8;
        int nr = min(8, n - r0);
        // load 8 rows into smem (float4, coalesced)
#pragma unroll
        for (int t = 0; t < 4; t++) {
            int idx = lane + 32 * t;       // 0..127 float4 slots
            int r = idx >> 4, c4 = idx & 15;
            float4 v = (r < nr) ? ((const float4*)(hs + (size_t)(r0 + r) * 64))[c4]
                                : make_float4(0.f, 0.f, 0.f, 0.f);
            ((float4*)rows)[idx] = v;
        }
        __syncwarp();

        // ---- phase 1: t = relu(hs @ wA.T + bA) ----
        unsigned long long acc[8][2];
#pragma unroll
        for (int i = 0; i < 8; i++) { acc[i][0] = 0ull; acc[i][1] = 0ull; }
#pragma unroll 4
        for (int k2 = 0; k2 < 32; k2++) {
            unsigned long long w0, w1;
            asm volatile("ld.shared.v2.u64 {%0,%1}, [%2];"
                         : "=l"(w0), "=l"(w1) : "r"(wA_a + (k2 * 32 + lane) * 16));
#pragma unroll
            for (int i = 0; i < 8; i++) {
                unsigned long long h2;
                asm volatile("ld.shared.b64 %0, [%1];"
                             : "=l"(h2) : "r"(rows_a + i * 256 + k2 * 8));
                ffma2(acc[i][0], h2, w0);
                ffma2(acc[i][1], h2, w1);
            }
        }
#pragma unroll
        for (int i = 0; i < 8; i++) {
            ts[i * 64 + lane] = fmaxf(f32x2_sum(acc[i][0]) + bAj0, 0.f);
            ts[i * 64 + lane + 32] = fmaxf(f32x2_sum(acc[i][1]) + bAj1, 0.f);
        }
        __syncwarp();

        // ---- phase 2: out = relu(t @ wB.T + bB) ----
#pragma unroll
        for (int i = 0; i < 8; i++) { acc[i][0] = 0ull; acc[i][1] = 0ull; }
#pragma unroll 4
        for (int k2 = 0; k2 < 32; k2++) {
            unsigned long long w0, w1;
            asm volatile("ld.shared.v2.u64 {%0,%1}, [%2];"
                         : "=l"(w0), "=l"(w1) : "r"(wB_a + (k2 * 32 + lane) * 16));
#pragma unroll
            for (int i = 0; i < 8; i++) {
                unsigned long long h2;
                asm volatile("ld.shared.b64 %0, [%1];"
                             : "=l"(h2) : "r"(ts_a + i * 256 + k2 * 8));
                ffma2(acc[i][0], h2, w0);
                ffma2(acc[i][1], h2, w1);
            }
        }
        for (int i = 0; i < nr; i++) {
            out[(size_t)(r0 + i) * 64 + lane] = fmaxf(f32x2_sum(acc[i][0]) + bBj0, 0.f);
            out[(size_t)(r0 + i) * 64 + lane + 32] = fmaxf(f32x2_sum(acc[i][1]) + bBj1, 0.f);
        }
        __syncwarp();
    }
}

// ---------------- mean-pool over sorted batch ----------------
__global__ void pool_kernel(const float* __restrict__ h,
                            const int* __restrict__ batch, int n,
                            float* __restrict__ sums, float* __restrict__ cnt) {
    int d = threadIdx.x & 63;
    int sub = threadIdx.x >> 6;           // 0..3
    int start = blockIdx.x * POOL_CHUNK + sub;
    int end = min(blockIdx.x * POOL_CHUNK + POOL_CHUNK, n);
    float acc = 0.f, c = 0.f;
    int cur = -1;
    for (int r = start; r < end; r += 4) {
        int b = __ldg(batch + r);
        if (b != cur) {
            if (cur >= 0) {
                atomicAdd(&sums[cur * 64 + d], acc);
                if (d == 0) atomicAdd(&cnt[cur], c);
            }
            cur = b; acc = 0.f; c = 0.f;
        }
        acc += h[(size_t)r * 64 + d];
        c += 1.f;
    }
    if (cur >= 0) {
        atomicAdd(&sums[cur * 64 + d], acc);
        if (d == 0) atomicAdd(&cnt[cur], c);
    }
}

// ---------------- LSTM gate GEMM ----------------
__global__ void __launch_bounds__(512) gates_kernel(
        const float* __restrict__ sums, const float* __restrict__ cnt,
        const float* __restrict__ h0,
        const float* __restrict__ w_ih, const float* __restrict__ w_hh,
        const float* __restrict__ b_ih, const float* __restrict__ b_hh,
        float* __restrict__ gates) {
    int b = blockIdx.x;
    int j = threadIdx.x;
    __shared__ float ps[64];
    __shared__ float h0s[128];
    if (j < 64) ps[j] = sums[b * 64 + j] / fmaxf(cnt[b], 1.f);
    if (j >= 64 && j < 192) h0s[j - 64] = h0[b * 128 + (j - 64)];
    __syncthreads();

    float acc = b_ih[j] + b_hh[j];
    const float4* wi = (const float4*)(w_ih + (size_t)j * 64);
#pragma unroll
    for (int k4 = 0; k4 < 16; k4++) {
        float4 w = __ldg(wi + k4);
        acc += w.x * ps[k4 * 4] + w.y * ps[k4 * 4 + 1]
             + w.z * ps[k4 * 4 + 2] + w.w * ps[k4 * 4 + 3];
    }
    const float4* wh = (const float4*)(w_hh + (size_t)j * 128);
#pragma unroll
    for (int k4 = 0; k4 < 32; k4++) {
        float4 w = __ldg(wh + k4);
        acc += w.x * h0s[k4 * 4] + w.y * h0s[k4 * 4 + 1]
             + w.z * h0s[k4 * 4 + 2] + w.w * h0s[k4 * 4 + 3];
    }
    gates[b * 512 + j] = acc;
}

// ---------------- LSTM cell + FC + softmax ----------------
__global__ void lstm_fc_kernel(const float* __restrict__ gates,
                               const float* __restrict__ c0,
                               const float* __restrict__ fc_w,
                               const float* __restrict__ fc_b,
                               float* __restrict__ out) {
    int b = blockIdx.x;
    int t = threadIdx.x;  // 128
    __shared__ float h1s[128];
    const float* gb = gates + b * 512;
    float gi = gb[t], gf = gb[128 + t], gg = gb[256 + t], go = gb[384 + t];
    float si = 1.f / (1.f + expf(-gi));
    float sf = 1.f / (1.f + expf(-gf));
    float so = 1.f / (1.f + expf(-go));
    float c1 = sf * c0[b * 128 + t] + si * tanhf(gg);
    float h1 = so * tanhf(c1);
    out[B * 32 + b * 128 + t] = h1;
    out[B * 32 + B * 128 + b * 128 + t] = c1;
    h1s[t] = h1;
    __syncthreads();
    if (t < 32) {
        float acc = fc_b[t];
        const float4* fw = (const float4*)(fc_w + (size_t)t * 128);
#pragma unroll
        for (int k4 = 0; k4 < 32; k4++) {
            float4 w = __ldg(fw + k4);
            acc += w.x * h1s[k4 * 4] + w.y * h1s[k4 * 4 + 1]
                 + w.z * h1s[k4 * 4 + 2] + w.w * h1s[k4 * 4 + 3];
        }
        float m = acc;
        for (int off = 16; off; off >>= 1)
            m = fmaxf(m, __shfl_xor_sync(0xffffffffu, m, off));
        float e = expf(acc - m);
        float s = e;
        for (int off = 16; off; off >>= 1)
            s += __shfl_xor_sync(0xffffffffu, s, off);
        out[b * 32 + t] = e / s;
    }
}

// ---------------- launch ----------------
extern "C" void kernel_launch(void* const* d_in, const int* in_sizes, int n_in,
                              void* d_out, int out_size) {
    const float* x     = (const float*)d_in[0];
    const int*   ei    = (const int*)d_in[1];
    const int*   batch = (const int*)d_in[2];
    const float* w1    = (const float*)d_in[3];
    const float* b1    = (const float*)d_in[4];
    const float* w2    = (const float*)d_in[5];
    const float* b2    = (const float*)d_in[6];
    const float* w3    = (const float*)d_in[7];
    const float* b3    = (const float*)d_in[8];
    const float* w4    = (const float*)d_in[9];
    const float* b4    = (const float*)d_in[10];
    const float* w_ih  = (const float*)d_in[11];
    const float* w_hh  = (const float*)d_in[12];
    const float* b_ih  = (const float*)d_in[13];
    const float* b_hh  = (const float*)d_in[14];
    const float* fc_w  = (const float*)d_in[15];
    const float* fc_b  = (const float*)d_in[16];
    const float* h0    = (const float*)d_in[17];
    const float* c0    = (const float*)d_in[18];
    float* out = (float*)d_out;

    int n_nodes = in_sizes[0] / 64;
    int n_edges = in_sizes[1] / 2;

    int* counts;   cudaGetSymbolAddress((void**)&counts, g_counts);
    int* offs;     cudaGetSymbolAddress((void**)&offs, g_offs);
    int* cursor;   cudaGetSymbolAddress((void**)&cursor, g_cursor);
    int* chunkbase;cudaGetSymbolAddress((void**)&chunkbase, g_chunkbase);
    int* elist;    cudaGetSymbolAddress((void**)&elist, g_elist);
    float* hs;     cudaGetSymbolAddress((void**)&hs, g_hs);
    float* h1;     cudaGetSymbolAddress((void**)&h1, g_h1);
    float* sums;   cudaGetSymbolAddress((void**)&sums, g_sums);
    float* cnt;    cudaGetSymbolAddress((void**)&cnt, g_cnt);
    float* gates;  cudaGetSymbolAddress((void**)&gates, g_gates);

    static bool attr_set = false;
    if (!attr_set) {
        cudaFuncSetAttribute(gin_kernel, cudaFuncAttributeMaxDynamicSharedMemorySize,
                             GIN_SMEM_FLOATS * 4);
        attr_set = true;
    }

    int eb = (n_edges + 255) / 256;
    int nb = (n_nodes + 255) / 256;
    int gather_blocks = (n_nodes * 32 + 255) / 256;
    int gin_blocks = 444;  // 148 SMs * 3 (smem-limited)
    int pool_blocks = (n_nodes + POOL_CHUNK - 1) / POOL_CHUNK;

    // ---- CSR build (reused by both layers) ----
    zero_all_kernel<<<nb, 256>>>(counts, sums, cnt, n_nodes);
    count_kernel<<<eb, 256>>>(ei, n_edges, counts);
    scan1_kernel<<<1, NCH>>>(counts, n_nodes, chunkbase);
    scan2_kernel<<<2, 256>>>(counts, n_nodes, chunkbase, offs, cursor);
    fill_kernel<<<eb, 256>>>(ei, n_edges, cursor, elist);

    // ---- layer 1 ----
    gather_kernel<<<gather_blocks, 256>>>(x, x, elist, offs, counts, hs, n_nodes);
    gin_kernel<<<gin_blocks, 256, GIN_SMEM_FLOATS * 4>>>(hs, w1, b1, w2, b2, h1, n_nodes);

    // ---- layer 2 ----
    gather_kernel<<<gather_blocks, 256>>>(h1, h1, elist, offs, counts, hs, n_nodes);
    gin_kernel<<<gin_blocks, 256, GIN_SMEM_FLOATS * 4>>>(hs, w3, b3, w4, b4, h1, n_nodes);

    // ---- pooling ----
    pool_kernel<<<pool_blocks, 256>>>(h1, batch, n_nodes, sums, cnt);

    // ---- LSTM + FC + softmax ----
    gates_kernel<<<B, 512>>>(sums, cnt, h0, w_ih, w_hh, b_ih, b_hh, gates);
    lstm_fc_kernel<<<B, 128>>>(gates, c0, fc_w, fc_b, out);
}

// round 3
// speedup vs baseline: 1.2404x; 1.1591x over previous
#include <cuda_runtime.h>
#include <math.h>

#define MAX_NODES 50000
#define NPAD_CAP 51200          // padded capacity (multiple of 1024)
#define MAX_EDGES 800000
#define D 64
#define B 64
#define HL 128
#define SCAN_TILE 1024
#define POOL_CHUNK 1024

// ---------------- scratch (device globals; no allocation) ----------------
__device__ int g_counts[NPAD_CAP];
__device__ int g_offs[NPAD_CAP];
__device__ int g_cursor[NPAD_CAP];
__device__ int g_blocksums[64];
__device__ int g_elist[MAX_EDGES];
__device__ __align__(16) float g_hs[MAX_NODES * D];   // gather output (x + sum)
__device__ __align__(16) float g_h1[MAX_NODES * D];   // gin output
__device__ __align__(16) float g_sums[B * D];
__device__ float g_cnt[B];
__device__ __align__(16) float g_gates[B * 4 * HL];

// ---------------- zero counts (padded) + pool accumulators ----------------
__global__ void zero_all_kernel(int* counts, float* sums, float* cnt, int npad) {
    int i = blockIdx.x * blockDim.x + threadIdx.x;
    if (i < npad) counts[i] = 0;
    if (i < B * D) sums[i] = 0.f;
    if (i < B) cnt[i] = 0.f;
}

// ---------------- CSR build ----------------
__global__ void count_kernel(const int* __restrict__ ei, int n_edges,
                             int* __restrict__ counts) {
    int e = blockIdx.x * blockDim.x + threadIdx.x;
    if (e < n_edges) atomicAdd(&counts[__ldg(ei + n_edges + e)], 1);
}

// Phase A: per-block coalesced scan (int4 per thread), local exclusive + block sum
__global__ void __launch_bounds__(256) scanA_kernel(
        const int* __restrict__ counts, int* __restrict__ offs,
        int* __restrict__ blocksums) {
    __shared__ int wsum[8];
    int t = threadIdx.x;
    int lane = t & 31, warp = t >> 5;
    int idx = blockIdx.x * SCAN_TILE + t * 4;
    int4 v = *(const int4*)(counts + idx);
    int s = v.x + v.y + v.z + v.w;
    int incl = s;
#pragma unroll
    for (int off = 1; off < 32; off <<= 1) {
        int u = __shfl_up_sync(0xffffffffu, incl, off);
        if (lane >= off) incl += u;
    }
    if (lane == 31) wsum[warp] = incl;
    __syncthreads();
    if (warp == 0) {
        int ws = (lane < 8) ? wsum[lane] : 0;
#pragma unroll
        for (int off = 1; off < 8; off <<= 1) {
            int u = __shfl_up_sync(0xffffffffu, ws, off);
            if (lane >= off) ws += u;
        }
        if (lane < 8) wsum[lane] = ws;
    }
    __syncthreads();
    int wbase = warp ? wsum[warp - 1] : 0;
    int ebase = wbase + incl - s;
    int4 e;
    e.x = ebase; e.y = ebase + v.x; e.z = e.y + v.y; e.w = e.z + v.z;
    *(int4*)(offs + idx) = e;
    if (t == 255) blocksums[blockIdx.x] = wsum[7];
}

// Phase B: scan the (<=64) block sums -> exclusive bases
__global__ void scanB_kernel(int* blocksums, int nb) {
    __shared__ int sm[64];
    int t = threadIdx.x;  // 64
    int v = (t < nb) ? blocksums[t] : 0;
    sm[t] = v;
    __syncthreads();
    for (int off = 1; off < 64; off <<= 1) {
        int u = (t >= off) ? sm[t - off] : 0;
        __syncthreads();
        sm[t] += u;
        __syncthreads();
    }
    if (t < nb) blocksums[t] = sm[t] - v;
}

// Phase C: add block base; write offs + cursor
__global__ void __launch_bounds__(256) scanC_kernel(
        int* __restrict__ offs, int* __restrict__ cursor,
        const int* __restrict__ blocksums) {
    int idx = blockIdx.x * SCAN_TILE + threadIdx.x * 4;
    int base = __ldg(blocksums + blockIdx.x);
    int4 e = *(int4*)(offs + idx);
    e.x += base; e.y += base; e.z += base; e.w += base;
    *(int4*)(offs + idx) = e;
    *(int4*)(cursor + idx) = e;
}

__global__ void fill_kernel(const int* __restrict__ ei, int n_edges,
                            int* __restrict__ cursor, int* __restrict__ elist) {
    int e = blockIdx.x * blockDim.x + threadIdx.x;
    if (e < n_edges) {
        int s = __ldg(ei + e);
        int d = __ldg(ei + n_edges + e);
        int p = atomicAdd(&cursor[d], 1);
        elist[p] = s;
    }
}

// ---------------- CSR gather: outh[i] = x[i] + sum_{j in N(i)} feat[j] ----
__global__ void __launch_bounds__(256) gather_kernel(
        const float* __restrict__ feat, const float* __restrict__ xin,
        const int* __restrict__ elist, const int* __restrict__ offs,
        const int* __restrict__ counts, float* __restrict__ outh, int n) {
    int w = (blockIdx.x * blockDim.x + threadIdx.x) >> 5;
    int lane = threadIdx.x & 31;
    if (w >= n) return;
    int start = __ldg(offs + w);
    int deg = __ldg(counts + w);
    float2 a0 = ((const float2*)(xin + (size_t)w * 64))[lane];
    float2 a1 = make_float2(0.f, 0.f);
    float2 a2 = make_float2(0.f, 0.f);
    float2 a3 = make_float2(0.f, 0.f);
    int e = 0;
    for (; e + 3 < deg; e += 4) {
        int s0 = __ldg(elist + start + e);
        int s1 = __ldg(elist + start + e + 1);
        int s2 = __ldg(elist + start + e + 2);
        int s3 = __ldg(elist + start + e + 3);
        float2 v0 = ((const float2*)(feat + (size_t)s0 * 64))[lane];
        float2 v1 = ((const float2*)(feat + (size_t)s1 * 64))[lane];
        float2 v2 = ((const float2*)(feat + (size_t)s2 * 64))[lane];
        float2 v3 = ((const float2*)(feat + (size_t)s3 * 64))[lane];
        a0.x += v0.x; a0.y += v0.y;
        a1.x += v1.x; a1.y += v1.y;
        a2.x += v2.x; a2.y += v2.y;
        a3.x += v3.x; a3.y += v3.y;
    }
    for (; e < deg; e++) {
        int s0 = __ldg(elist + start + e);
        float2 v0 = ((const float2*)(feat + (size_t)s0 * 64))[lane];
        a0.x += v0.x; a0.y += v0.y;
    }
    float2 r = make_float2(a0.x + a1.x + a2.x + a3.x,
                           a0.y + a1.y + a2.y + a3.y);
    ((float2*)(outh + (size_t)w * 64))[lane] = r;
}

// ---------------- fused GIN MLP via packed f32x2 FMA ----------------
#define GIN_SMEM_FLOATS 16512

__device__ __forceinline__ void ffma2(unsigned long long& acc,
                                      unsigned long long a, unsigned long long b) {
    asm("fma.rn.f32x2 %0, %1, %2, %3;" : "=l"(acc) : "l"(a), "l"(b), "l"(acc));
}
__device__ __forceinline__ float f32x2_sum(unsigned long long v) {
    float lo = __uint_as_float((unsigned)(v & 0xffffffffull));
    float hi = __uint_as_float((unsigned)(v >> 32));
    return lo + hi;
}

__global__ void __launch_bounds__(256) gin_kernel(
        const float* __restrict__ hs,
        const float* __restrict__ wA, const float* __restrict__ bA,
        const float* __restrict__ wB, const float* __restrict__ bB,
        float* __restrict__ out, int n) {
    extern __shared__ float smem[];
    float4* wA4 = (float4*)smem;
    float4* wB4 = (float4*)(smem + 4096);
    float* rowsbuf = smem + 8192;
    float* tsbuf = smem + 12288;
    float* bAs = smem + 16384;
    float* bBs = smem + 16448;

    int tid = threadIdx.x, warp = tid >> 5, lane = tid & 31;
    for (int idx = tid; idx < 1024; idx += 256) {
        int j0 = idx & 31, k = (idx >> 5) * 2;
        wA4[idx] = make_float4(wA[j0 * 64 + k], wA[j0 * 64 + k + 1],
                               wA[(j0 + 32) * 64 + k], wA[(j0 + 32) * 64 + k + 1]);
        wB4[idx] = make_float4(wB[j0 * 64 + k], wB[j0 * 64 + k + 1],
                               wB[(j0 + 32) * 64 + k], wB[(j0 + 32) * 64 + k + 1]);
    }
    if (tid < 64) { bAs[tid] = bA[tid]; bBs[tid] = bB[tid]; }
    __syncthreads();

    float* rows = rowsbuf + warp * 512;
    float* ts = tsbuf + warp * 512;
    unsigned rows_a = (unsigned)__cvta_generic_to_shared(rows);
    unsigned ts_a = (unsigned)__cvta_generic_to_shared(ts);
    unsigned wA_a = (unsigned)__cvta_generic_to_shared(wA4);
    unsigned wB_a = (unsigned)__cvta_generic_to_shared(wB4);

    float bAj0 = bAs[lane], bAj1 = bAs[lane + 32];
    float bBj0 = bBs[lane], bBj1 = bBs[lane + 32];

    int ngroups = (n + 7) >> 3;
    for (int g = blockIdx.x * 8 + warp; g < ngroups; g += gridDim.x * 8) {
        int r0 = g * 8;
        int nr = min(8, n - r0);
#pragma unroll
        for (int t = 0; t < 4; t++) {
            int idx = lane + 32 * t;
            int r = idx >> 4, c4 = idx & 15;
            float4 v = (r < nr) ? ((const float4*)(hs + (size_t)(r0 + r) * 64))[c4]
                                : make_float4(0.f, 0.f, 0.f, 0.f);
            ((float4*)rows)[idx] = v;
        }
        __syncwarp();

        unsigned long long acc[8][2];
#pragma unroll
        for (int i = 0; i < 8; i++) { acc[i][0] = 0ull; acc[i][1] = 0ull; }
#pragma unroll 4
        for (int k2 = 0; k2 < 32; k2++) {
            unsigned long long w0, w1;
            asm volatile("ld.shared.v2.u64 {%0,%1}, [%2];"
                         : "=l"(w0), "=l"(w1) : "r"(wA_a + (k2 * 32 + lane) * 16));
#pragma unroll
            for (int i = 0; i < 8; i++) {
                unsigned long long h2;
                asm volatile("ld.shared.b64 %0, [%1];"
                             : "=l"(h2) : "r"(rows_a + i * 256 + k2 * 8));
                ffma2(acc[i][0], h2, w0);
                ffma2(acc[i][1], h2, w1);
            }
        }
#pragma unroll
        for (int i = 0; i < 8; i++) {
            ts[i * 64 + lane] = fmaxf(f32x2_sum(acc[i][0]) + bAj0, 0.f);
            ts[i * 64 + lane + 32] = fmaxf(f32x2_sum(acc[i][1]) + bAj1, 0.f);
        }
        __syncwarp();

#pragma unroll
        for (int i = 0; i < 8; i++) { acc[i][0] = 0ull; acc[i][1] = 0ull; }
#pragma unroll 4
        for (int k2 = 0; k2 < 32; k2++) {
            unsigned long long w0, w1;
            asm volatile("ld.shared.v2.u64 {%0,%1}, [%2];"
                         : "=l"(w0), "=l"(w1) : "r"(wB_a + (k2 * 32 + lane) * 16));
#pragma unroll
            for (int i = 0; i < 8; i++) {
                unsigned long long h2;
                asm volatile("ld.shared.b64 %0, [%1];"
                             : "=l"(h2) : "r"(ts_a + i * 256 + k2 * 8));
                ffma2(acc[i][0], h2, w0);
                ffma2(acc[i][1], h2, w1);
            }
        }
        for (int i = 0; i < nr; i++) {
            out[(size_t)(r0 + i) * 64 + lane] = fmaxf(f32x2_sum(acc[i][0]) + bBj0, 0.f);
            out[(size_t)(r0 + i) * 64 + lane + 32] = fmaxf(f32x2_sum(acc[i][1]) + bBj1, 0.f);
        }
        __syncwarp();
    }
}

// ---------------- mean-pool over sorted batch ----------------
__global__ void pool_kernel(const float* __restrict__ h,
                            const int* __restrict__ batch, int n,
                            float* __restrict__ sums, float* __restrict__ cnt) {
    int d = threadIdx.x & 63;
    int sub = threadIdx.x >> 6;
    int start = blockIdx.x * POOL_CHUNK + sub;
    int end = min(blockIdx.x * POOL_CHUNK + POOL_CHUNK, n);
    float acc = 0.f, c = 0.f;
    int cur = -1;
    for (int r = start; r < end; r += 4) {
        int b = __ldg(batch + r);
        if (b != cur) {
            if (cur >= 0) {
                atomicAdd(&sums[cur * 64 + d], acc);
                if (d == 0) atomicAdd(&cnt[cur], c);
            }
            cur = b; acc = 0.f; c = 0.f;
        }
        acc += h[(size_t)r * 64 + d];
        c += 1.f;
    }
    if (cur >= 0) {
        atomicAdd(&sums[cur * 64 + d], acc);
        if (d == 0) atomicAdd(&cnt[cur], c);
    }
}

// ---------------- LSTM gate GEMM ----------------
__global__ void __launch_bounds__(512) gates_kernel(
        const float* __restrict__ sums, const float* __restrict__ cnt,
        const float* __restrict__ h0,
        const float* __restrict__ w_ih, const float* __restrict__ w_hh,
        const float* __restrict__ b_ih, const float* __restrict__ b_hh,
        float* __restrict__ gates) {
    int b = blockIdx.x;
    int j = threadIdx.x;
    __shared__ float ps[64];
    __shared__ float h0s[128];
    if (j < 64) ps[j] = sums[b * 64 + j] / fmaxf(cnt[b], 1.f);
    if (j >= 64 && j < 192) h0s[j - 64] = h0[b * 128 + (j - 64)];
    __syncthreads();

    float acc = b_ih[j] + b_hh[j];
    const float4* wi = (const float4*)(w_ih + (size_t)j * 64);
#pragma unroll
    for (int k4 = 0; k4 < 16; k4++) {
        float4 w = __ldg(wi + k4);
        acc += w.x * ps[k4 * 4] + w.y * ps[k4 * 4 + 1]
             + w.z * ps[k4 * 4 + 2] + w.w * ps[k4 * 4 + 3];
    }
    const float4* wh = (const float4*)(w_hh + (size_t)j * 128);
#pragma unroll
    for (int k4 = 0; k4 < 32; k4++) {
        float4 w = __ldg(wh + k4);
        acc += w.x * h0s[k4 * 4] + w.y * h0s[k4 * 4 + 1]
             + w.z * h0s[k4 * 4 + 2] + w.w * h0s[k4 * 4 + 3];
    }
    gates[b * 512 + j] = acc;
}

// ---------------- LSTM cell + FC + softmax ----------------
__global__ void lstm_fc_kernel(const float* __restrict__ gates,
                               const float* __restrict__ c0,
                               const float* __restrict__ fc_w,
                               const float* __restrict__ fc_b,
                               float* __restrict__ out) {
    int b = blockIdx.x;
    int t = threadIdx.x;
    __shared__ float h1s[128];
    const float* gb = gates + b * 512;
    float gi = gb[t], gf = gb[128 + t], gg = gb[256 + t], go = gb[384 + t];
    float si = 1.f / (1.f + expf(-gi));
    float sf = 1.f / (1.f + expf(-gf));
    float so = 1.f / (1.f + expf(-go));
    float c1 = sf * c0[b * 128 + t] + si * tanhf(gg);
    float h1 = so * tanhf(c1);
    out[B * 32 + b * 128 + t] = h1;
    out[B * 32 + B * 128 + b * 128 + t] = c1;
    h1s[t] = h1;
    __syncthreads();
    if (t < 32) {
        float acc = fc_b[t];
        const float4* fw = (const float4*)(fc_w + (size_t)t * 128);
#pragma unroll
        for (int k4 = 0; k4 < 32; k4++) {
            float4 w = __ldg(fw + k4);
            acc += w.x * h1s[k4 * 4] + w.y * h1s[k4 * 4 + 1]
                 + w.z * h1s[k4 * 4 + 2] + w.w * h1s[k4 * 4 + 3];
        }
        float m = acc;
        for (int off = 16; off; off >>= 1)
            m = fmaxf(m, __shfl_xor_sync(0xffffffffu, m, off));
        float e = expf(acc - m);
        float s = e;
        for (int off = 16; off; off >>= 1)
            s += __shfl_xor_sync(0xffffffffu, s, off);
        out[b * 32 + t] = e / s;
    }
}

// ---------------- launch ----------------
extern "C" void kernel_launch(void* const* d_in, const int* in_sizes, int n_in,
                              void* d_out, int out_size) {
    const float* x     = (const float*)d_in[0];
    const int*   ei    = (const int*)d_in[1];
    const int*   batch = (const int*)d_in[2];
    const float* w1    = (const float*)d_in[3];
    const float* b1    = (const float*)d_in[4];
    const float* w2    = (const float*)d_in[5];
    const float* b2    = (const float*)d_in[6];
    const float* w3    = (const float*)d_in[7];
    const float* b3    = (const float*)d_in[8];
    const float* w4    = (const float*)d_in[9];
    const float* b4    = (const float*)d_in[10];
    const float* w_ih  = (const float*)d_in[11];
    const float* w_hh  = (const float*)d_in[12];
    const float* b_ih  = (const float*)d_in[13];
    const float* b_hh  = (const float*)d_in[14];
    const float* fc_w  = (const float*)d_in[15];
    const float* fc_b  = (const float*)d_in[16];
    const float* h0    = (const float*)d_in[17];
    const float* c0    = (const float*)d_in[18];
    float* out = (float*)d_out;

    int n_nodes = in_sizes[0] / 64;
    int n_edges = in_sizes[1] / 2;
    int npad = (n_nodes + SCAN_TILE - 1) & ~(SCAN_TILE - 1);
    int nsb = npad / SCAN_TILE;   // scan blocks (<=64 by capacity)

    int* counts;    cudaGetSymbolAddress((void**)&counts, g_counts);
    int* offs;      cudaGetSymbolAddress((void**)&offs, g_offs);
    int* cursor;    cudaGetSymbolAddress((void**)&cursor, g_cursor);
    int* blocksums; cudaGetSymbolAddress((void**)&blocksums, g_blocksums);
    int* elist;     cudaGetSymbolAddress((void**)&elist, g_elist);
    float* hs;      cudaGetSymbolAddress((void**)&hs, g_hs);
    float* h1;      cudaGetSymbolAddress((void**)&h1, g_h1);
    float* sums;    cudaGetSymbolAddress((void**)&sums, g_sums);
    float* cnt;     cudaGetSymbolAddress((void**)&cnt, g_cnt);
    float* gates;   cudaGetSymbolAddress((void**)&gates, g_gates);

    cudaFuncSetAttribute(gin_kernel, cudaFuncAttributeMaxDynamicSharedMemorySize,
                         GIN_SMEM_FLOATS * 4);

    int eb = (n_edges + 255) / 256;
    int zb = (npad + 255) / 256;
    int gather_blocks = (n_nodes * 32 + 255) / 256;
    int gin_blocks = 444;
    int pool_blocks = (n_nodes + POOL_CHUNK - 1) / POOL_CHUNK;

    // ---- CSR build (reused by both layers) ----
    zero_all_kernel<<<zb, 256>>>(counts, sums, cnt, npad);
    count_kernel<<<eb, 256>>>(ei, n_edges, counts);
    scanA_kernel<<<nsb, 256>>>(counts, offs, blocksums);
    scanB_kernel<<<1, 64>>>(blocksums, nsb);
    scanC_kernel<<<nsb, 256>>>(offs, cursor, blocksums);
    fill_kernel<<<eb, 256>>>(ei, n_edges, cursor, elist);

    // ---- layer 1 ----
    gather_kernel<<<gather_blocks, 256>>>(x, x, elist, offs, counts, hs, n_nodes);
    gin_kernel<<<gin_blocks, 256, GIN_SMEM_FLOATS * 4>>>(hs, w1, b1, w2, b2, h1, n_nodes);

    // ---- layer 2 ----
    gather_kernel<<<gather_blocks, 256>>>(h1, h1, elist, offs, counts, hs, n_nodes);
    gin_kernel<<<gin_blocks, 256, GIN_SMEM_FLOATS * 4>>>(hs, w3, b3, w4, b4, h1, n_nodes);

    // ---- pooling ----
    pool_kernel<<<pool_blocks, 256>>>(h1, batch, n_nodes, sums, cnt);

    // ---- LSTM + FC + softmax ----
    gates_kernel<<<B, 512>>>(sums, cnt, h0, w_ih, w_hh, b_ih, b_hh, gates);
    lstm_fc_kernel<<<B, 128>>>(gates, c0, fc_w, fc_b, out);
}